// round 16
// baseline (speedup 1.0000x reference)
#include <cuda_runtime.h>
#include <cuda_fp16.h>
#include <mma.h>
#include <math.h>

using namespace nvcuda;

#define NN 100000
#define EE 1600000
#define FIN 128
#define HID 32
#define HEADS 8
#define D1 256        // HEADS*HID
#define NCLS 40
#define BETA 0.1f
#define ONE_MB 0.9f   // 1-beta
#define LRA 0.2f      // leaky relu alpha
#define SCB 1024
#define NBLK ((NN + SCB - 1) / SCB)

// ------------- scratch (device globals; total ~185 MB, < 256 MB) -------------
__device__ __align__(128) __half g_H16[(size_t)NN * D1];  // features fp16
__device__ __align__(128) __half g_FA16[(size_t)NN * 128];// hop-1 intermediate (fp16)
__device__ __align__(128) __half g_X16[(size_t)NN * FIN]; // x in fp16 (for wmma)
__device__ __align__(128) __half g_W16w[FIN * D1];        // W in fp16, [k][col]
__device__ __align__(128) __half g_O16[(size_t)NN * NCLS];// H @ W_out (fp16)
__device__ __align__(128) __half g_GA16[(size_t)NN * NCLS];// layer-2 hop-1 (fp16)
__device__ __align__(128) __half g_W16[2][(size_t)EE * 4];// unnorm attn w (fp16, packed)
__device__ __align__(128) int    g_SSRC[EE];              // src sorted by dst (CSR)
__device__ __align__(128) __half g_S16[(size_t)NN * 8];   // per-node S, 8 heads fp16
__device__ __align__(128) float  g_T8[(size_t)NN * 8];    // per-node T, fp32 (dst-only)
__device__ __align__(128) float  g_INV8[(size_t)NN * 8];  // per-dst 1/denom
__device__ __align__(128) float  g_SL2[NN];               // layer-2 s (fp32)
__device__ __align__(128) float  g_TL2[NN];               // layer-2 t (fp32)
__device__ int   g_ROWPTR[NN + 1];
__device__ int   g_DEG[NN];
__device__ int   g_CUR[NN];
__device__ int   g_BSUM[NBLK];
__device__ int   g_BOFF[NBLK];
__device__ int   g_EI64;

// ------------------------------- helpers --------------------------------------
__device__ __forceinline__ float warp_sum(float v) {
#pragma unroll
    for (int o = 16; o > 0; o >>= 1) v += __shfl_xor_sync(0xffffffffu, v, o);
    return v;
}
__device__ __forceinline__ float warp_max(float v) {
#pragma unroll
    for (int o = 16; o > 0; o >>= 1) v = fmaxf(v, __shfl_xor_sync(0xffffffffu, v, o));
    return v;
}
__device__ __forceinline__ int warp_sum_i(int v) {
#pragma unroll
    for (int o = 16; o > 0; o >>= 1) v += __shfl_xor_sync(0xffffffffu, v, o);
    return v;
}
__device__ __forceinline__ float sel4(float4 w, int h) {
    return (h == 0) ? w.x : (h == 1) ? w.y : (h == 2) ? w.z : w.w;
}
__device__ __forceinline__ float4 ld4h(const __half* p, int idx4) {
    uint2 u = ((const uint2*)p)[idx4];
    float2 f0 = __half22float2(*(__half2*)&u.x);
    float2 f1 = __half22float2(*(__half2*)&u.y);
    return make_float4(f0.x, f0.y, f1.x, f1.y);
}
__device__ __forceinline__ void st4h(__half* p, int idx4, float4 v) {
    __half2 pa = __floats2half2_rn(v.x, v.y);
    __half2 pb = __floats2half2_rn(v.z, v.w);
    uint2 u;
    u.x = *(unsigned*)&pa;
    u.y = *(unsigned*)&pb;
    ((uint2*)p)[idx4] = u;
}

// ------------------------- edge dtype sniff (parallel) -------------------------
__global__ void sniff_kernel(const int* __restrict__ ei32) {
    int bad = 0;
    for (int i = threadIdx.x; i < 512; i += 256)
        bad |= (ei32[2 * i + 1] != 0);
    bad = __syncthreads_or(bad);
    if (threadIdx.x == 0) g_EI64 = bad ? 0 : 1;
}

__device__ __forceinline__ int load_node(const void* ei, size_t pos, int is64) {
    if (is64) return (int)((const long long*)ei)[pos];
    return ((const int*)ei)[pos];
}

// ------------------------------ CSR build -------------------------------------
__global__ void zero_counts_kernel() {
    int i = blockIdx.x * blockDim.x + threadIdx.x;
    if (i < NN) { g_DEG[i] = 0; g_CUR[i] = 0; }
}

__global__ void build_deg_kernel(const void* __restrict__ ei) {
    int e = blockIdx.x * blockDim.x + threadIdx.x;
    if (e >= EE) return;
    int d = load_node(ei, (size_t)EE + e, g_EI64);
    if ((unsigned)d < NN) atomicAdd(&g_DEG[d], 1);
}

__global__ void scanA_kernel() {
    __shared__ int wsum[8];
    int tid = threadIdx.x;
    int base = blockIdx.x * SCB + tid * 4;
    int s = 0;
#pragma unroll
    for (int j = 0; j < 4; j++) { int i = base + j; if (i < NN) s += g_DEG[i]; }
    s = warp_sum_i(s);
    if ((tid & 31) == 0) wsum[tid >> 5] = s;
    __syncthreads();
    if (tid == 0) {
        int t = 0;
#pragma unroll
        for (int w = 0; w < 8; w++) t += wsum[w];
        g_BSUM[blockIdx.x] = t;
    }
}

__global__ void scanB_kernel() {
    __shared__ int sm[4];
    int tid = threadIdx.x, lane = tid & 31, wid = tid >> 5;
    int v = (tid < NBLK) ? g_BSUM[tid] : 0;
    int x = v;
#pragma unroll
    for (int o = 1; o < 32; o <<= 1) {
        int y = __shfl_up_sync(0xffffffffu, x, o);
        if (lane >= o) x += y;
    }
    if (lane == 31) sm[wid] = x;
    __syncthreads();
    int woff = 0;
    for (int w = 0; w < wid; w++) woff += sm[w];
    if (tid < NBLK) g_BOFF[tid] = woff + x - v;
}

__global__ void scanC_kernel() {
    __shared__ int wsum[8];
    int tid = threadIdx.x, lane = tid & 31, wid = tid >> 5;
    int base = blockIdx.x * SCB + tid * 4;
    int a0 = (base + 0 < NN) ? g_DEG[base + 0] : 0;
    int a1 = (base + 1 < NN) ? g_DEG[base + 1] : 0;
    int a2 = (base + 2 < NN) ? g_DEG[base + 2] : 0;
    int a3 = (base + 3 < NN) ? g_DEG[base + 3] : 0;
    int tsum = a0 + a1 + a2 + a3;
    int x = tsum;
#pragma unroll
    for (int o = 1; o < 32; o <<= 1) {
        int y = __shfl_up_sync(0xffffffffu, x, o);
        if (lane >= o) x += y;
    }
    if (lane == 31) wsum[wid] = x;
    __syncthreads();
    int woff = 0;
    for (int w = 0; w < wid; w++) woff += wsum[w];
    int excl = g_BOFF[blockIdx.x] + woff + (x - tsum);
    if (base + 0 < NN) g_ROWPTR[base + 1] = excl + a0;
    if (base + 1 < NN) g_ROWPTR[base + 2] = excl + a0 + a1;
    if (base + 2 < NN) g_ROWPTR[base + 3] = excl + a0 + a1 + a2;
    if (base + 3 < NN) g_ROWPTR[base + 4] = excl + tsum;
    if (blockIdx.x == 0 && tid == 0) g_ROWPTR[0] = 0;
}

__global__ void scatter_kernel(const void* __restrict__ ei) {
    int e = blockIdx.x * blockDim.x + threadIdx.x;
    if (e >= EE) return;
    int is64 = g_EI64;
    int s = load_node(ei, (size_t)e, is64);
    int d = load_node(ei, (size_t)EE + e, is64);
    if ((unsigned)d >= NN || (unsigned)s >= NN) return;
    int pos = g_ROWPTR[d] + atomicAdd(&g_CUR[d], 1);
    if ((unsigned)pos < EE) g_SSRC[pos] = s;
}

// --------------------------- fp16 input conversion ----------------------------
__global__ void cvtx_kernel(const float* __restrict__ x) {
    size_t idx = (size_t)(blockIdx.x * blockDim.x + threadIdx.x) * 4;
    if (idx >= (size_t)NN * FIN) return;
    float4 v = *(const float4*)&x[idx];
    st4h(g_X16, (int)(idx >> 2), v);
}

__global__ void cvtw_kernel(const float* __restrict__ W) {
    int idx = blockIdx.x * blockDim.x + threadIdx.x;
    if (idx >= FIN * D1) return;
    int k = idx / D1;
    int col = idx % D1;
    float v = W[(size_t)(col >> 5) * (FIN * HID) + (size_t)k * HID + (col & 31)];
    g_W16w[idx] = __float2half_rn(v);
}

// --------------- GEMM1: wmma fp16 tensor cores, 64x128 block tile -------------
__global__ void __launch_bounds__(256) gemm1_kernel() {
    __shared__ __half As[64][24];
    __shared__ __half Bs[16][136];
    __shared__ float  Cs[8][16][16];
    int tid = threadIdx.x, warp = tid >> 5, lane = tid & 31;
    int wm = warp & 1, wn = warp >> 1;
    int rowBase = blockIdx.x * 64;
    int colBase = blockIdx.y * 128;
    wmma::fragment<wmma::accumulator, 16, 16, 16, float> c[2][2];
#pragma unroll
    for (int i = 0; i < 2; i++)
#pragma unroll
        for (int j = 0; j < 2; j++)
            wmma::fill_fragment(c[i][j], 0.0f);

    for (int kt = 0; kt < FIN; kt += 16) {
        {
            int r = tid >> 2;
            int cq = (tid & 3) * 4;
            int gr = rowBase + r;
            uint2 u = make_uint2(0u, 0u);
            if (gr < NN) u = *(const uint2*)&g_X16[(size_t)gr * FIN + kt + cq];
            *(uint2*)&As[r][cq] = u;
        }
#pragma unroll
        for (int p = 0; p < 2; p++) {
            int idx = tid + p * 256;
            int k = idx >> 5;
            int cq = (idx & 31) * 4;
            *(uint2*)&Bs[k][cq] = *(const uint2*)&g_W16w[(size_t)(kt + k) * D1 + colBase + cq];
        }
        __syncthreads();
        wmma::fragment<wmma::matrix_a, 16, 16, 16, __half, wmma::row_major> a[2];
        wmma::fragment<wmma::matrix_b, 16, 16, 16, __half, wmma::row_major> b[2];
#pragma unroll
        for (int i = 0; i < 2; i++)
            wmma::load_matrix_sync(a[i], &As[wm * 32 + i * 16][0], 24);
#pragma unroll
        for (int j = 0; j < 2; j++)
            wmma::load_matrix_sync(b[j], &Bs[0][wn * 32 + j * 16], 136);
#pragma unroll
        for (int i = 0; i < 2; i++)
#pragma unroll
            for (int j = 0; j < 2; j++)
                wmma::mma_sync(c[i][j], a[i], b[j], c[i][j]);
        __syncthreads();
    }
#pragma unroll
    for (int i = 0; i < 2; i++)
#pragma unroll
        for (int j = 0; j < 2; j++) {
            wmma::store_matrix_sync(&Cs[warp][0][0], c[i][j], 16, wmma::mem_row_major);
            __syncwarp();
            int r0 = lane >> 1;
            int c0 = (lane & 1) * 8;
            int gr = rowBase + wm * 32 + i * 16 + r0;
            if (gr < NN) {
                float* src = &Cs[warp][r0][c0];
                __half2 h0 = __floats2half2_rn(src[0], src[1]);
                __half2 h1 = __floats2half2_rn(src[2], src[3]);
                __half2 h2 = __floats2half2_rn(src[4], src[5]);
                __half2 h3 = __floats2half2_rn(src[6], src[7]);
                uint4 u;
                u.x = *(unsigned*)&h0; u.y = *(unsigned*)&h1;
                u.z = *(unsigned*)&h2; u.w = *(unsigned*)&h3;
                *(uint4*)&g_H16[(size_t)gr * D1 + colBase + wn * 32 + j * 16 + c0] = u;
            }
            __syncwarp();
        }
}

// ---- GEMM2 (fp16 A-rows) + fused st40; writes O16 (fp16) and SL2/TL2 ---------
__global__ void gemm2_kernel(const float* __restrict__ Wout,
                             const float* __restrict__ a_so,
                             const float* __restrict__ a_do) {
    __shared__ float Bs[D1 * NCLS];
    __shared__ float As_[NCLS], Ad_[NCLS];
    int tid = threadIdx.x;
    for (int i = tid; i < D1 * NCLS; i += 256) Bs[i] = Wout[i];
    if (tid < NCLS) { As_[tid] = a_so[tid]; Ad_[tid] = a_do[tid]; }
    __syncthreads();
    int row = blockIdx.x * 256 + tid;
    if (row >= NN) return;
    const __half2* arow = (const __half2*)(g_H16 + (size_t)row * D1);
    float acc[NCLS] = {};
#pragma unroll 2
    for (int k2 = 0; k2 < D1 / 2; k2++) {
        float2 a2 = __half22float2(__ldg(arow + k2));
        const float* b0 = &Bs[(2 * k2) * NCLS];
        const float* b1 = &Bs[(2 * k2 + 1) * NCLS];
#pragma unroll
        for (int c = 0; c < NCLS; c++) acc[c] += a2.x * b0[c] + a2.y * b1[c];
    }
    __half* orow16 = g_O16 + (size_t)row * NCLS;
    float s = 0.f, t = 0.f;
#pragma unroll
    for (int c = 0; c < NCLS; c++) {
        orow16[c] = __float2half_rn(acc[c]);
        s += acc[c] * As_[c];
        t += acc[c] * Ad_[c];
    }
    g_SL2[row] = s;
    g_TL2[row] = t;
}

// --------------------- attention s,t for ALL 8 heads at once ------------------
__global__ void st8_kernel(const float* __restrict__ a_src,
                           const float* __restrict__ a_dst) {
    int gw = blockIdx.x * 8 + (threadIdx.x >> 5);
    int lane = threadIdx.x & 31;
    if (gw >= NN) return;
    const __half* row = g_H16 + (size_t)gw * D1;
#pragma unroll
    for (int h = 0; h < HEADS; h++) {
        float v = __half2float(row[h * HID + lane]);
        float s = warp_sum(v * a_src[h * HID + lane]);
        float t = warp_sum(v * a_dst[h * HID + lane]);
        if (lane == 0) {
            g_S16[(size_t)gw * 8 + h] = __float2half_rn(s);
            g_T8[(size_t)gw * 8 + h] = t;
        }
    }
}

// ----- 8-head fused attention weights (unnormalized, fp16-stored) + INV --------
__global__ void attn8_kernel() {
    int d = blockIdx.x * 8 + (threadIdx.x >> 5);
    int lane = threadIdx.x & 31;
    if (d >= NN) return;
    int start = g_ROWPTR[d], end = g_ROWPTR[d + 1];
    if (start == end) {
        if (lane == 0) {
            float4 z = make_float4(0.f, 0.f, 0.f, 0.f);
            *(float4*)&g_INV8[(size_t)d * 8] = z;
            *(float4*)&g_INV8[(size_t)d * 8 + 4] = z;
        }
        return;
    }
    float4 ta = *(const float4*)&g_T8[(size_t)d * 8];
    float4 tb = *(const float4*)&g_T8[(size_t)d * 8 + 4];
    float t[8] = {ta.x, ta.y, ta.z, ta.w, tb.x, tb.y, tb.z, tb.w};
    float m[8];
#pragma unroll
    for (int i = 0; i < 8; i++) m[i] = -INFINITY;
    for (int e = start + lane; e < end; e += 32) {
        int s = g_SSRC[e];
        float4 sa = ld4h(g_S16 + (size_t)s * 8, 0);
        float4 sb = ld4h(g_S16 + (size_t)s * 8, 1);
        float sv[8] = {sa.x, sa.y, sa.z, sa.w, sb.x, sb.y, sb.z, sb.w};
#pragma unroll
        for (int i = 0; i < 8; i++) {
            float ev = sv[i] + t[i];
            ev = (ev >= 0.f) ? ev : LRA * ev;
            m[i] = fmaxf(m[i], ev);
        }
    }
#pragma unroll
    for (int i = 0; i < 8; i++) m[i] = warp_max(m[i]);
    float u[8] = {};
    for (int e = start + lane; e < end; e += 32) {
        int s = g_SSRC[e];
        float4 sa = ld4h(g_S16 + (size_t)s * 8, 0);
        float4 sb = ld4h(g_S16 + (size_t)s * 8, 1);
        float sv[8] = {sa.x, sa.y, sa.z, sa.w, sb.x, sb.y, sb.z, sb.w};
        float p[8];
#pragma unroll
        for (int i = 0; i < 8; i++) {
            float ev = sv[i] + t[i];
            ev = (ev >= 0.f) ? ev : LRA * ev;
            p[i] = __expf(ev - m[i]);
            u[i] += p[i];
        }
        st4h(g_W16[0], e, make_float4(p[0], p[1], p[2], p[3]));
        st4h(g_W16[1], e, make_float4(p[4], p[5], p[6], p[7]));
    }
#pragma unroll
    for (int i = 0; i < 8; i++) u[i] = warp_sum(u[i]);
    if (lane == 0) {
        *(float4*)&g_INV8[(size_t)d * 8] =
            make_float4(1.f / (u[0] + 1e-16f), 1.f / (u[1] + 1e-16f),
                        1.f / (u[2] + 1e-16f), 1.f / (u[3] + 1e-16f));
        *(float4*)&g_INV8[(size_t)d * 8 + 4] =
            make_float4(1.f / (u[4] + 1e-16f), 1.f / (u[5] + 1e-16f),
                        1.f / (u[6] + 1e-16f), 1.f / (u[7] + 1e-16f));
    }
}

// --------- 4-head fused diffusion hop, fp16 gathers + fp16 weights ------------
__global__ void hop4_kernel(int g, int mode) {
    int d = blockIdx.x * 8 + (threadIdx.x >> 5);
    int lane = threadIdx.x & 31;
    if (d >= NN) return;
    int h = lane >> 3;
    int start = g_ROWPTR[d], end = g_ROWPTR[d + 1];
    const __half* wb = g_W16[g];
    float4 acc = make_float4(0.f, 0.f, 0.f, 0.f);
    int e = start;
    for (; e + 4 <= end; e += 4) {
        int s0 = g_SSRC[e], s1 = g_SSRC[e + 1], s2 = g_SSRC[e + 2], s3 = g_SSRC[e + 3];
        float4 w0 = ld4h(wb, e);
        float4 w1 = ld4h(wb, e + 1);
        float4 w2 = ld4h(wb, e + 2);
        float4 w3 = ld4h(wb, e + 3);
        const __half *r0, *r1, *r2, *r3;
        if (mode == 0) {
            r0 = g_H16 + (size_t)s0 * D1 + g * 128;
            r1 = g_H16 + (size_t)s1 * D1 + g * 128;
            r2 = g_H16 + (size_t)s2 * D1 + g * 128;
            r3 = g_H16 + (size_t)s3 * D1 + g * 128;
        } else {
            r0 = g_FA16 + (size_t)s0 * 128;
            r1 = g_FA16 + (size_t)s1 * 128;
            r2 = g_FA16 + (size_t)s2 * 128;
            r3 = g_FA16 + (size_t)s3 * 128;
        }
        float4 v0 = ld4h(r0, lane), v1 = ld4h(r1, lane);
        float4 v2 = ld4h(r2, lane), v3 = ld4h(r3, lane);
        float wv0 = sel4(w0, h), wv1 = sel4(w1, h), wv2 = sel4(w2, h), wv3 = sel4(w3, h);
        acc.x += wv0 * v0.x + wv1 * v1.x + wv2 * v2.x + wv3 * v3.x;
        acc.y += wv0 * v0.y + wv1 * v1.y + wv2 * v2.y + wv3 * v3.y;
        acc.z += wv0 * v0.z + wv1 * v1.z + wv2 * v2.z + wv3 * v3.z;
        acc.w += wv0 * v0.w + wv1 * v1.w + wv2 * v2.w + wv3 * v3.w;
    }
    for (; e < end; e++) {
        int s0 = g_SSRC[e];
        float4 w0 = ld4h(wb, e);
        const __half* r0 = (mode == 0)
            ? g_H16 + (size_t)s0 * D1 + g * 128
            : g_FA16 + (size_t)s0 * 128;
        float4 v0 = ld4h(r0, lane);
        float wv0 = sel4(w0, h);
        acc.x += wv0 * v0.x; acc.y += wv0 * v0.y;
        acc.z += wv0 * v0.z; acc.w += wv0 * v0.w;
    }
    float4 inv4 = *(const float4*)&g_INV8[(size_t)d * 8 + g * 4];
    float invv = sel4(inv4, h);
    __half* h0p = g_H16 + (size_t)d * D1 + g * 128;
    float4 h0v = ld4h(h0p, lane);
    float4 v;
    v.x = ONE_MB * acc.x * invv + BETA * h0v.x;
    v.y = ONE_MB * acc.y * invv + BETA * h0v.y;
    v.z = ONE_MB * acc.z * invv + BETA * h0v.z;
    v.w = ONE_MB * acc.w * invv + BETA * h0v.w;
    if (mode == 0) {
        st4h(g_FA16 + (size_t)d * 128, lane, v);
    } else {
        v.x = (v.x > 0.f) ? v.x : expm1f(v.x);
        v.y = (v.y > 0.f) ? v.y : expm1f(v.y);
        v.z = (v.z > 0.f) ? v.z : expm1f(v.z);
        v.w = (v.w > 0.f) ? v.w : expm1f(v.w);
        st4h(h0p, lane, v);
    }
}

// ------------------------------ output layer -----------------------------------
// 2-pass: max, then sum + write UNNORMALIZED fp16 p; inv stored in INV8[d*8].
__global__ void attn_w_kernel() {
    int d = blockIdx.x * 8 + (threadIdx.x >> 5);
    int lane = threadIdx.x & 31;
    if (d >= NN) return;
    int start = g_ROWPTR[d], end = g_ROWPTR[d + 1];
    if (start == end) return;   // acc=0 in hop40 regardless of stale inv
    __half* wb = g_W16[0];
    float td = g_TL2[d];
    float m = -INFINITY;
    for (int e = start + lane; e < end; e += 32) {
        float ev = g_SL2[g_SSRC[e]] + td;
        ev = (ev >= 0.f) ? ev : LRA * ev;
        m = fmaxf(m, ev);
    }
    m = warp_max(m);
    float sum = 0.f;
    for (int e = start + lane; e < end; e += 32) {
        float ev = g_SL2[g_SSRC[e]] + td;
        ev = (ev >= 0.f) ? ev : LRA * ev;
        float p = __expf(ev - m);
        wb[e] = __float2half_rn(p);
        sum += p;
    }
    sum = warp_sum(sum);
    if (lane == 0) g_INV8[(size_t)d * 8] = 1.f / (sum + 1e-16f);
}

__global__ void hop40_kernel(int mode, float* __restrict__ out) {
    int d = blockIdx.x * 8 + (threadIdx.x >> 5);
    int lane = threadIdx.x & 31;
    if (d >= NN) return;
    int start = g_ROWPTR[d], end = g_ROWPTR[d + 1];
    float acca = 0.f, accb = 0.f;
    bool hi = (lane < 8);
    const __half* base = (mode == 0) ? g_O16 : g_GA16;
    const __half* wb = g_W16[0];
    int e = start;
    for (; e + 4 <= end; e += 4) {
        int s0 = g_SSRC[e], s1 = g_SSRC[e + 1], s2 = g_SSRC[e + 2], s3 = g_SSRC[e + 3];
        float w0 = __half2float(wb[e]);
        float w1 = __half2float(wb[e + 1]);
        float w2 = __half2float(wb[e + 2]);
        float w3 = __half2float(wb[e + 3]);
        const __half* r0 = base + (size_t)s0 * NCLS;
        const __half* r1 = base + (size_t)s1 * NCLS;
        const __half* r2 = base + (size_t)s2 * NCLS;
        const __half* r3 = base + (size_t)s3 * NCLS;
        acca += w0 * __half2float(r0[lane]) + w1 * __half2float(r1[lane])
              + w2 * __half2float(r2[lane]) + w3 * __half2float(r3[lane]);
        if (hi)
            accb += w0 * __half2float(r0[32 + lane]) + w1 * __half2float(r1[32 + lane])
                  + w2 * __half2float(r2[32 + lane]) + w3 * __half2float(r3[32 + lane]);
    }
    for (; e < end; e++) {
        int s = g_SSRC[e];
        float w = __half2float(wb[e]);
        const __half* row = base + (size_t)s * NCLS;
        acca += w * __half2float(row[lane]);
        if (hi) accb += w * __half2float(row[32 + lane]);
    }
    float invv = g_INV8[(size_t)d * 8];
    const __half* h0row = g_O16 + (size_t)d * NCLS;
    float va = ONE_MB * acca * invv + BETA * __half2float(h0row[lane]);
    float vb = hi ? (ONE_MB * accb * invv + BETA * __half2float(h0row[32 + lane])) : 0.f;
    if (mode == 0) {
        __half* orow = g_GA16 + (size_t)d * NCLS;
        orow[lane] = __float2half_rn(va);
        if (hi) orow[32 + lane] = __float2half_rn(vb);
    } else {
        float ea = (va > 0.f) ? va : expm1f(va);
        float eb = hi ? ((vb > 0.f) ? vb : expm1f(vb)) : -INFINITY;
        float mx = warp_max(fmaxf(ea, eb));
        float se = expf(ea - mx) + (hi ? expf(eb - mx) : 0.f);
        se = warp_sum(se);
        float lse = mx + logf(se);
        float* orow = out + (size_t)d * NCLS;
        orow[lane] = ea - lse;
        if (hi) orow[32 + lane] = eb - lse;
    }
}

// --------------------------------- launch -------------------------------------
extern "C" void kernel_launch(void* const* d_in, const int* in_sizes, int n_in,
                              void* d_out, int out_size) {
    const float* x     = (const float*)d_in[0];
    const void*  ei    = d_in[1];
    const float* W     = (const float*)d_in[2];
    const float* a_src = (const float*)d_in[3];
    const float* a_dst = (const float*)d_in[4];
    const float* Wout  = (const float*)d_in[5];
    const float* a_so  = (const float*)d_in[6];
    const float* a_do  = (const float*)d_in[7];
    float*       out   = (float*)d_out;

    const int NWARP_GRID = (NN + 7) / 8;
    const int EGRID = (EE + 255) / 256;
    const int NGRID = (NN + 255) / 256;

    sniff_kernel<<<1, 256>>>((const int*)ei);
    zero_counts_kernel<<<NGRID, 256>>>();
    build_deg_kernel<<<EGRID, 256>>>(ei);
    scanA_kernel<<<NBLK, 256>>>();
    scanB_kernel<<<1, 128>>>();
    scanC_kernel<<<NBLK, 256>>>();
    scatter_kernel<<<EGRID, 256>>>(ei);

    cvtx_kernel<<<(NN * FIN / 4 + 255) / 256, 256>>>(x);
    cvtw_kernel<<<(FIN * D1 + 255) / 256, 256>>>(W);
    gemm1_kernel<<<dim3((NN + 63) / 64, D1 / 128), 256>>>();
    st8_kernel<<<NWARP_GRID, 256>>>(a_src, a_dst);
    attn8_kernel<<<NWARP_GRID, 256>>>();

    for (int g = 0; g < 2; g++) {
        hop4_kernel<<<NWARP_GRID, 256>>>(g, 0);
        hop4_kernel<<<NWARP_GRID, 256>>>(g, 1);
    }

    gemm2_kernel<<<(NN + 255) / 256, 256>>>(Wout, a_so, a_do);

    attn_w_kernel<<<NWARP_GRID, 256>>>();
    hop40_kernel<<<NWARP_GRID, 256>>>(0, nullptr);
    hop40_kernel<<<NWARP_GRID, 256>>>(1, out);
}

// round 17
// speedup vs baseline: 1.0413x; 1.0413x over previous
#include <cuda_runtime.h>
#include <cuda_fp16.h>
#include <mma.h>
#include <math.h>

using namespace nvcuda;

#define NN 100000
#define EE 1600000
#define FIN 128
#define HID 32
#define HEADS 8
#define D1 256        // HEADS*HID
#define NCLS 40
#define BETA 0.1f
#define ONE_MB 0.9f   // 1-beta
#define LRA 0.2f      // leaky relu alpha
#define SCB 1024
#define NBLK ((NN + SCB - 1) / SCB)

// ------------- scratch (device globals; total ~185 MB, < 256 MB) -------------
__device__ __align__(128) __half g_H16[(size_t)NN * D1];  // features fp16
__device__ __align__(128) __half g_FA16[(size_t)NN * 128];// hop-1 intermediate (fp16)
__device__ __align__(128) __half g_X16[(size_t)NN * FIN]; // x in fp16 (for wmma)
__device__ __align__(128) __half g_W16w[FIN * D1];        // W in fp16, [k][col]
__device__ __align__(128) __half g_O16[(size_t)NN * NCLS];// H @ W_out (fp16)
__device__ __align__(128) __half g_GA16[(size_t)NN * NCLS];// layer-2 hop-1 (fp16)
__device__ __align__(128) __half g_W16[2][(size_t)EE * 4];// unnorm attn w (fp16, packed)
__device__ __align__(128) int    g_SSRC[EE];              // src sorted by dst (CSR)
__device__ __align__(128) __half g_S16[(size_t)NN * 8];   // per-node S, 8 heads fp16
__device__ __align__(128) float  g_T8[(size_t)NN * 8];    // per-node T, fp32 (dst-only)
__device__ __align__(128) float  g_INV8[(size_t)NN * 8];  // per-dst 1/denom
__device__ __align__(128) float  g_SL2[NN];               // layer-2 s (fp32)
__device__ __align__(128) float  g_TL2[NN];               // layer-2 t (fp32)
__device__ int   g_ROWPTR[NN + 1];
__device__ int   g_DEG[NN];
__device__ int   g_CUR[NN];
__device__ int   g_BSUM[NBLK];
__device__ int   g_BOFF[NBLK];
__device__ int   g_EI64;

// ------------------------------- helpers --------------------------------------
__device__ __forceinline__ float warp_sum(float v) {
#pragma unroll
    for (int o = 16; o > 0; o >>= 1) v += __shfl_xor_sync(0xffffffffu, v, o);
    return v;
}
__device__ __forceinline__ float warp_max(float v) {
#pragma unroll
    for (int o = 16; o > 0; o >>= 1) v = fmaxf(v, __shfl_xor_sync(0xffffffffu, v, o));
    return v;
}
__device__ __forceinline__ int warp_sum_i(int v) {
#pragma unroll
    for (int o = 16; o > 0; o >>= 1) v += __shfl_xor_sync(0xffffffffu, v, o);
    return v;
}
__device__ __forceinline__ float sel4(float4 w, int h) {
    return (h == 0) ? w.x : (h == 1) ? w.y : (h == 2) ? w.z : w.w;
}
__device__ __forceinline__ float4 ld4h(const __half* p, int idx4) {
    uint2 u = ((const uint2*)p)[idx4];
    float2 f0 = __half22float2(*(__half2*)&u.x);
    float2 f1 = __half22float2(*(__half2*)&u.y);
    return make_float4(f0.x, f0.y, f1.x, f1.y);
}
__device__ __forceinline__ void st4h(__half* p, int idx4, float4 v) {
    __half2 pa = __floats2half2_rn(v.x, v.y);
    __half2 pb = __floats2half2_rn(v.z, v.w);
    uint2 u;
    u.x = *(unsigned*)&pa;
    u.y = *(unsigned*)&pb;
    ((uint2*)p)[idx4] = u;
}

// ------------------------- edge dtype sniff (parallel) -------------------------
__global__ void sniff_kernel(const int* __restrict__ ei32) {
    int bad = 0;
    for (int i = threadIdx.x; i < 512; i += 256)
        bad |= (ei32[2 * i + 1] != 0);
    bad = __syncthreads_or(bad);
    if (threadIdx.x == 0) g_EI64 = bad ? 0 : 1;
}

__device__ __forceinline__ int load_node(const void* ei, size_t pos, int is64) {
    if (is64) return (int)((const long long*)ei)[pos];
    return ((const int*)ei)[pos];
}

// ------------------------------ CSR build -------------------------------------
__global__ void zero_counts_kernel() {
    int i = blockIdx.x * blockDim.x + threadIdx.x;
    if (i < NN) { g_DEG[i] = 0; g_CUR[i] = 0; }
}

__global__ void build_deg_kernel(const void* __restrict__ ei) {
    int e = blockIdx.x * blockDim.x + threadIdx.x;
    if (e >= EE) return;
    int d = load_node(ei, (size_t)EE + e, g_EI64);
    if ((unsigned)d < NN) atomicAdd(&g_DEG[d], 1);
}

__global__ void scanA_kernel() {
    __shared__ int wsum[8];
    int tid = threadIdx.x;
    int base = blockIdx.x * SCB + tid * 4;
    int s = 0;
#pragma unroll
    for (int j = 0; j < 4; j++) { int i = base + j; if (i < NN) s += g_DEG[i]; }
    s = warp_sum_i(s);
    if ((tid & 31) == 0) wsum[tid >> 5] = s;
    __syncthreads();
    if (tid == 0) {
        int t = 0;
#pragma unroll
        for (int w = 0; w < 8; w++) t += wsum[w];
        g_BSUM[blockIdx.x] = t;
    }
}

__global__ void scanB_kernel() {
    __shared__ int sm[4];
    int tid = threadIdx.x, lane = tid & 31, wid = tid >> 5;
    int v = (tid < NBLK) ? g_BSUM[tid] : 0;
    int x = v;
#pragma unroll
    for (int o = 1; o < 32; o <<= 1) {
        int y = __shfl_up_sync(0xffffffffu, x, o);
        if (lane >= o) x += y;
    }
    if (lane == 31) sm[wid] = x;
    __syncthreads();
    int woff = 0;
    for (int w = 0; w < wid; w++) woff += sm[w];
    if (tid < NBLK) g_BOFF[tid] = woff + x - v;
}

__global__ void scanC_kernel() {
    __shared__ int wsum[8];
    int tid = threadIdx.x, lane = tid & 31, wid = tid >> 5;
    int base = blockIdx.x * SCB + tid * 4;
    int a0 = (base + 0 < NN) ? g_DEG[base + 0] : 0;
    int a1 = (base + 1 < NN) ? g_DEG[base + 1] : 0;
    int a2 = (base + 2 < NN) ? g_DEG[base + 2] : 0;
    int a3 = (base + 3 < NN) ? g_DEG[base + 3] : 0;
    int tsum = a0 + a1 + a2 + a3;
    int x = tsum;
#pragma unroll
    for (int o = 1; o < 32; o <<= 1) {
        int y = __shfl_up_sync(0xffffffffu, x, o);
        if (lane >= o) x += y;
    }
    if (lane == 31) wsum[wid] = x;
    __syncthreads();
    int woff = 0;
    for (int w = 0; w < wid; w++) woff += wsum[w];
    int excl = g_BOFF[blockIdx.x] + woff + (x - tsum);
    if (base + 0 < NN) g_ROWPTR[base + 1] = excl + a0;
    if (base + 1 < NN) g_ROWPTR[base + 2] = excl + a0 + a1;
    if (base + 2 < NN) g_ROWPTR[base + 3] = excl + a0 + a1 + a2;
    if (base + 3 < NN) g_ROWPTR[base + 4] = excl + tsum;
    if (blockIdx.x == 0 && tid == 0) g_ROWPTR[0] = 0;
}

__global__ void scatter_kernel(const void* __restrict__ ei) {
    int e = blockIdx.x * blockDim.x + threadIdx.x;
    if (e >= EE) return;
    int is64 = g_EI64;
    int s = load_node(ei, (size_t)e, is64);
    int d = load_node(ei, (size_t)EE + e, is64);
    if ((unsigned)d >= NN || (unsigned)s >= NN) return;
    int pos = g_ROWPTR[d] + atomicAdd(&g_CUR[d], 1);
    if ((unsigned)pos < EE) g_SSRC[pos] = s;
}

// --------------------------- fp16 input conversion ----------------------------
__global__ void cvtx_kernel(const float* __restrict__ x) {
    size_t idx = (size_t)(blockIdx.x * blockDim.x + threadIdx.x) * 4;
    if (idx >= (size_t)NN * FIN) return;
    float4 v = *(const float4*)&x[idx];
    st4h(g_X16, (int)(idx >> 2), v);
}

__global__ void cvtw_kernel(const float* __restrict__ W) {
    int idx = blockIdx.x * blockDim.x + threadIdx.x;
    if (idx >= FIN * D1) return;
    int k = idx / D1;
    int col = idx % D1;
    float v = W[(size_t)(col >> 5) * (FIN * HID) + (size_t)k * HID + (col & 31)];
    g_W16w[idx] = __float2half_rn(v);
}

// --------------- GEMM1: wmma fp16 tensor cores, 64x128 block tile -------------
__global__ void __launch_bounds__(256) gemm1_kernel() {
    __shared__ __half As[64][24];
    __shared__ __half Bs[16][136];
    __shared__ float  Cs[8][16][16];
    int tid = threadIdx.x, warp = tid >> 5, lane = tid & 31;
    int wm = warp & 1, wn = warp >> 1;
    int rowBase = blockIdx.x * 64;
    int colBase = blockIdx.y * 128;
    wmma::fragment<wmma::accumulator, 16, 16, 16, float> c[2][2];
#pragma unroll
    for (int i = 0; i < 2; i++)
#pragma unroll
        for (int j = 0; j < 2; j++)
            wmma::fill_fragment(c[i][j], 0.0f);

    for (int kt = 0; kt < FIN; kt += 16) {
        {
            int r = tid >> 2;
            int cq = (tid & 3) * 4;
            int gr = rowBase + r;
            uint2 u = make_uint2(0u, 0u);
            if (gr < NN) u = *(const uint2*)&g_X16[(size_t)gr * FIN + kt + cq];
            *(uint2*)&As[r][cq] = u;
        }
#pragma unroll
        for (int p = 0; p < 2; p++) {
            int idx = tid + p * 256;
            int k = idx >> 5;
            int cq = (idx & 31) * 4;
            *(uint2*)&Bs[k][cq] = *(const uint2*)&g_W16w[(size_t)(kt + k) * D1 + colBase + cq];
        }
        __syncthreads();
        wmma::fragment<wmma::matrix_a, 16, 16, 16, __half, wmma::row_major> a[2];
        wmma::fragment<wmma::matrix_b, 16, 16, 16, __half, wmma::row_major> b[2];
#pragma unroll
        for (int i = 0; i < 2; i++)
            wmma::load_matrix_sync(a[i], &As[wm * 32 + i * 16][0], 24);
#pragma unroll
        for (int j = 0; j < 2; j++)
            wmma::load_matrix_sync(b[j], &Bs[0][wn * 32 + j * 16], 136);
#pragma unroll
        for (int i = 0; i < 2; i++)
#pragma unroll
            for (int j = 0; j < 2; j++)
                wmma::mma_sync(c[i][j], a[i], b[j], c[i][j]);
        __syncthreads();
    }
#pragma unroll
    for (int i = 0; i < 2; i++)
#pragma unroll
        for (int j = 0; j < 2; j++) {
            wmma::store_matrix_sync(&Cs[warp][0][0], c[i][j], 16, wmma::mem_row_major);
            __syncwarp();
            int r0 = lane >> 1;
            int c0 = (lane & 1) * 8;
            int gr = rowBase + wm * 32 + i * 16 + r0;
            if (gr < NN) {
                float* src = &Cs[warp][r0][c0];
                __half2 h0 = __floats2half2_rn(src[0], src[1]);
                __half2 h1 = __floats2half2_rn(src[2], src[3]);
                __half2 h2 = __floats2half2_rn(src[4], src[5]);
                __half2 h3 = __floats2half2_rn(src[6], src[7]);
                uint4 u;
                u.x = *(unsigned*)&h0; u.y = *(unsigned*)&h1;
                u.z = *(unsigned*)&h2; u.w = *(unsigned*)&h3;
                *(uint4*)&g_H16[(size_t)gr * D1 + colBase + wn * 32 + j * 16 + c0] = u;
            }
            __syncwarp();
        }
}

// ---- GEMM2 (fp16 A-rows) + fused st40; writes O16 (fp16) and SL2/TL2 ---------
__global__ void gemm2_kernel(const float* __restrict__ Wout,
                             const float* __restrict__ a_so,
                             const float* __restrict__ a_do) {
    __shared__ float Bs[D1 * NCLS];
    __shared__ float As_[NCLS], Ad_[NCLS];
    int tid = threadIdx.x;
    for (int i = tid; i < D1 * NCLS; i += 256) Bs[i] = Wout[i];
    if (tid < NCLS) { As_[tid] = a_so[tid]; Ad_[tid] = a_do[tid]; }
    __syncthreads();
    int row = blockIdx.x * 256 + tid;
    if (row >= NN) return;
    const __half2* arow = (const __half2*)(g_H16 + (size_t)row * D1);
    float acc[NCLS] = {};
#pragma unroll 2
    for (int k2 = 0; k2 < D1 / 2; k2++) {
        float2 a2 = __half22float2(__ldg(arow + k2));
        const float* b0 = &Bs[(2 * k2) * NCLS];
        const float* b1 = &Bs[(2 * k2 + 1) * NCLS];
#pragma unroll
        for (int c = 0; c < NCLS; c++) acc[c] += a2.x * b0[c] + a2.y * b1[c];
    }
    __half* orow16 = g_O16 + (size_t)row * NCLS;
    float s = 0.f, t = 0.f;
#pragma unroll
    for (int c = 0; c < NCLS; c++) {
        orow16[c] = __float2half_rn(acc[c]);
        s += acc[c] * As_[c];
        t += acc[c] * Ad_[c];
    }
    g_SL2[row] = s;
    g_TL2[row] = t;
}

// --------------------- attention s,t for ALL 8 heads at once ------------------
__global__ void st8_kernel(const float* __restrict__ a_src,
                           const float* __restrict__ a_dst) {
    int gw = blockIdx.x * 8 + (threadIdx.x >> 5);
    int lane = threadIdx.x & 31;
    if (gw >= NN) return;
    const __half* row = g_H16 + (size_t)gw * D1;
#pragma unroll
    for (int h = 0; h < HEADS; h++) {
        float v = __half2float(row[h * HID + lane]);
        float s = warp_sum(v * a_src[h * HID + lane]);
        float t = warp_sum(v * a_dst[h * HID + lane]);
        if (lane == 0) {
            g_S16[(size_t)gw * 8 + h] = __float2half_rn(s);
            g_T8[(size_t)gw * 8 + h] = t;
        }
    }
}

// ---- 8-head attention weights, SINGLE PASS (no max; logits bounded) + INV ----
__global__ void attn8_kernel() {
    int d = blockIdx.x * 8 + (threadIdx.x >> 5);
    int lane = threadIdx.x & 31;
    if (d >= NN) return;
    int start = g_ROWPTR[d], end = g_ROWPTR[d + 1];
    if (start == end) {
        if (lane == 0) {
            float4 z = make_float4(0.f, 0.f, 0.f, 0.f);
            *(float4*)&g_INV8[(size_t)d * 8] = z;
            *(float4*)&g_INV8[(size_t)d * 8 + 4] = z;
        }
        return;
    }
    float4 ta = *(const float4*)&g_T8[(size_t)d * 8];
    float4 tb = *(const float4*)&g_T8[(size_t)d * 8 + 4];
    float t[8] = {ta.x, ta.y, ta.z, ta.w, tb.x, tb.y, tb.z, tb.w};
    float u[8] = {};
    for (int e = start + lane; e < end; e += 32) {
        int s = g_SSRC[e];
        float4 sa = ld4h(g_S16 + (size_t)s * 8, 0);
        float4 sb = ld4h(g_S16 + (size_t)s * 8, 1);
        float sv[8] = {sa.x, sa.y, sa.z, sa.w, sb.x, sb.y, sb.z, sb.w};
        float p[8];
#pragma unroll
        for (int i = 0; i < 8; i++) {
            float ev = sv[i] + t[i];
            ev = (ev >= 0.f) ? ev : LRA * ev;
            p[i] = __expf(ev);
            u[i] += p[i];
        }
        st4h(g_W16[0], e, make_float4(p[0], p[1], p[2], p[3]));
        st4h(g_W16[1], e, make_float4(p[4], p[5], p[6], p[7]));
    }
#pragma unroll
    for (int i = 0; i < 8; i++) u[i] = warp_sum(u[i]);
    if (lane == 0) {
        *(float4*)&g_INV8[(size_t)d * 8] =
            make_float4(1.f / (u[0] + 1e-16f), 1.f / (u[1] + 1e-16f),
                        1.f / (u[2] + 1e-16f), 1.f / (u[3] + 1e-16f));
        *(float4*)&g_INV8[(size_t)d * 8 + 4] =
            make_float4(1.f / (u[4] + 1e-16f), 1.f / (u[5] + 1e-16f),
                        1.f / (u[6] + 1e-16f), 1.f / (u[7] + 1e-16f));
    }
}

// --------- 4-head fused diffusion hop, fp16 gathers + fp16 weights ------------
__global__ void hop4_kernel(int g, int mode) {
    int d = blockIdx.x * 8 + (threadIdx.x >> 5);
    int lane = threadIdx.x & 31;
    if (d >= NN) return;
    int h = lane >> 3;
    int start = g_ROWPTR[d], end = g_ROWPTR[d + 1];
    const __half* wb = g_W16[g];
    float4 acc = make_float4(0.f, 0.f, 0.f, 0.f);
    int e = start;
    for (; e + 4 <= end; e += 4) {
        int s0 = g_SSRC[e], s1 = g_SSRC[e + 1], s2 = g_SSRC[e + 2], s3 = g_SSRC[e + 3];
        float4 w0 = ld4h(wb, e);
        float4 w1 = ld4h(wb, e + 1);
        float4 w2 = ld4h(wb, e + 2);
        float4 w3 = ld4h(wb, e + 3);
        const __half *r0, *r1, *r2, *r3;
        if (mode == 0) {
            r0 = g_H16 + (size_t)s0 * D1 + g * 128;
            r1 = g_H16 + (size_t)s1 * D1 + g * 128;
            r2 = g_H16 + (size_t)s2 * D1 + g * 128;
            r3 = g_H16 + (size_t)s3 * D1 + g * 128;
        } else {
            r0 = g_FA16 + (size_t)s0 * 128;
            r1 = g_FA16 + (size_t)s1 * 128;
            r2 = g_FA16 + (size_t)s2 * 128;
            r3 = g_FA16 + (size_t)s3 * 128;
        }
        float4 v0 = ld4h(r0, lane), v1 = ld4h(r1, lane);
        float4 v2 = ld4h(r2, lane), v3 = ld4h(r3, lane);
        float wv0 = sel4(w0, h), wv1 = sel4(w1, h), wv2 = sel4(w2, h), wv3 = sel4(w3, h);
        acc.x += wv0 * v0.x + wv1 * v1.x + wv2 * v2.x + wv3 * v3.x;
        acc.y += wv0 * v0.y + wv1 * v1.y + wv2 * v2.y + wv3 * v3.y;
        acc.z += wv0 * v0.z + wv1 * v1.z + wv2 * v2.z + wv3 * v3.z;
        acc.w += wv0 * v0.w + wv1 * v1.w + wv2 * v2.w + wv3 * v3.w;
    }
    for (; e < end; e++) {
        int s0 = g_SSRC[e];
        float4 w0 = ld4h(wb, e);
        const __half* r0 = (mode == 0)
            ? g_H16 + (size_t)s0 * D1 + g * 128
            : g_FA16 + (size_t)s0 * 128;
        float4 v0 = ld4h(r0, lane);
        float wv0 = sel4(w0, h);
        acc.x += wv0 * v0.x; acc.y += wv0 * v0.y;
        acc.z += wv0 * v0.z; acc.w += wv0 * v0.w;
    }
    float4 inv4 = *(const float4*)&g_INV8[(size_t)d * 8 + g * 4];
    float invv = sel4(inv4, h);
    __half* h0p = g_H16 + (size_t)d * D1 + g * 128;
    float4 h0v = ld4h(h0p, lane);
    float4 v;
    v.x = ONE_MB * acc.x * invv + BETA * h0v.x;
    v.y = ONE_MB * acc.y * invv + BETA * h0v.y;
    v.z = ONE_MB * acc.z * invv + BETA * h0v.z;
    v.w = ONE_MB * acc.w * invv + BETA * h0v.w;
    if (mode == 0) {
        st4h(g_FA16 + (size_t)d * 128, lane, v);
    } else {
        v.x = (v.x > 0.f) ? v.x : expm1f(v.x);
        v.y = (v.y > 0.f) ? v.y : expm1f(v.y);
        v.z = (v.z > 0.f) ? v.z : expm1f(v.z);
        v.w = (v.w > 0.f) ? v.w : expm1f(v.w);
        st4h(h0p, lane, v);
    }
}

// ------------------------------ output layer -----------------------------------
// SINGLE pass (no max): unnormalized fp16 p, inv in INV8[d*8].
__global__ void attn_w_kernel() {
    int d = blockIdx.x * 8 + (threadIdx.x >> 5);
    int lane = threadIdx.x & 31;
    if (d >= NN) return;
    int start = g_ROWPTR[d], end = g_ROWPTR[d + 1];
    if (start == end) return;
    __half* wb = g_W16[0];
    float td = g_TL2[d];
    float sum = 0.f;
    for (int e = start + lane; e < end; e += 32) {
        float ev = g_SL2[g_SSRC[e]] + td;
        ev = (ev >= 0.f) ? ev : LRA * ev;
        float p = __expf(ev);
        wb[e] = __float2half_rn(p);
        sum += p;
    }
    sum = warp_sum(sum);
    if (lane == 0) g_INV8[(size_t)d * 8] = 1.f / (sum + 1e-16f);
}

__global__ void hop40_kernel(int mode, float* __restrict__ out) {
    int d = blockIdx.x * 8 + (threadIdx.x >> 5);
    int lane = threadIdx.x & 31;
    if (d >= NN) return;
    int start = g_ROWPTR[d], end = g_ROWPTR[d + 1];
    float acca = 0.f, accb = 0.f;
    bool hi = (lane < 8);
    const __half* base = (mode == 0) ? g_O16 : g_GA16;
    const __half* wb = g_W16[0];
    int e = start;
    for (; e + 4 <= end; e += 4) {
        int s0 = g_SSRC[e], s1 = g_SSRC[e + 1], s2 = g_SSRC[e + 2], s3 = g_SSRC[e + 3];
        float w0 = __half2float(wb[e]);
        float w1 = __half2float(wb[e + 1]);
        float w2 = __half2float(wb[e + 2]);
        float w3 = __half2float(wb[e + 3]);
        const __half* r0 = base + (size_t)s0 * NCLS;
        const __half* r1 = base + (size_t)s1 * NCLS;
        const __half* r2 = base + (size_t)s2 * NCLS;
        const __half* r3 = base + (size_t)s3 * NCLS;
        acca += w0 * __half2float(r0[lane]) + w1 * __half2float(r1[lane])
              + w2 * __half2float(r2[lane]) + w3 * __half2float(r3[lane]);
        if (hi)
            accb += w0 * __half2float(r0[32 + lane]) + w1 * __half2float(r1[32 + lane])
                  + w2 * __half2float(r2[32 + lane]) + w3 * __half2float(r3[32 + lane]);
    }
    for (; e < end; e++) {
        int s = g_SSRC[e];
        float w = __half2float(wb[e]);
        const __half* row = base + (size_t)s * NCLS;
        acca += w * __half2float(row[lane]);
        if (hi) accb += w * __half2float(row[32 + lane]);
    }
    float invv = g_INV8[(size_t)d * 8];
    const __half* h0row = g_O16 + (size_t)d * NCLS;
    float va = ONE_MB * acca * invv + BETA * __half2float(h0row[lane]);
    float vb = hi ? (ONE_MB * accb * invv + BETA * __half2float(h0row[32 + lane])) : 0.f;
    if (mode == 0) {
        __half* orow = g_GA16 + (size_t)d * NCLS;
        orow[lane] = __float2half_rn(va);
        if (hi) orow[32 + lane] = __float2half_rn(vb);
    } else {
        float ea = (va > 0.f) ? va : expm1f(va);
        float eb = hi ? ((vb > 0.f) ? vb : expm1f(vb)) : -INFINITY;
        float mx = warp_max(fmaxf(ea, eb));
        float se = expf(ea - mx) + (hi ? expf(eb - mx) : 0.f);
        se = warp_sum(se);
        float lse = mx + logf(se);
        float* orow = out + (size_t)d * NCLS;
        orow[lane] = ea - lse;
        if (hi) orow[32 + lane] = eb - lse;
    }
}

// --------------------------------- launch -------------------------------------
extern "C" void kernel_launch(void* const* d_in, const int* in_sizes, int n_in,
                              void* d_out, int out_size) {
    const float* x     = (const float*)d_in[0];
    const void*  ei    = d_in[1];
    const float* W     = (const float*)d_in[2];
    const float* a_src = (const float*)d_in[3];
    const float* a_dst = (const float*)d_in[4];
    const float* Wout  = (const float*)d_in[5];
    const float* a_so  = (const float*)d_in[6];
    const float* a_do  = (const float*)d_in[7];
    float*       out   = (float*)d_out;

    const int NWARP_GRID = (NN + 7) / 8;
    const int EGRID = (EE + 255) / 256;
    const int NGRID = (NN + 255) / 256;

    sniff_kernel<<<1, 256>>>((const int*)ei);
    zero_counts_kernel<<<NGRID, 256>>>();
    build_deg_kernel<<<EGRID, 256>>>(ei);
    scanA_kernel<<<NBLK, 256>>>();
    scanB_kernel<<<1, 128>>>();
    scanC_kernel<<<NBLK, 256>>>();
    scatter_kernel<<<EGRID, 256>>>(ei);

    cvtx_kernel<<<(NN * FIN / 4 + 255) / 256, 256>>>(x);
    cvtw_kernel<<<(FIN * D1 + 255) / 256, 256>>>(W);
    gemm1_kernel<<<dim3((NN + 63) / 64, D1 / 128), 256>>>();
    st8_kernel<<<NWARP_GRID, 256>>>(a_src, a_dst);
    attn8_kernel<<<NWARP_GRID, 256>>>();

    for (int g = 0; g < 2; g++) {
        hop4_kernel<<<NWARP_GRID, 256>>>(g, 0);
        hop4_kernel<<<NWARP_GRID, 256>>>(g, 1);
    }

    gemm2_kernel<<<(NN + 255) / 256, 256>>>(Wout, a_so, a_do);

    attn_w_kernel<<<NWARP_GRID, 256>>>();
    hop40_kernel<<<NWARP_GRID, 256>>>(0, nullptr);
    hop40_kernel<<<NWARP_GRID, 256>>>(1, out);
}